// round 1
// baseline (speedup 1.0000x reference)
#include <cuda_runtime.h>
#include <cuda_fp16.h>
#include <mma.h>

using namespace nvcuda;

#define H_DIM 4096
#define I_DIM 14336
#define M_DIM 8192   // B*S = 4*2048
#define BSQ   128    // quant blocksize

// ---------------- static device scratch (no allocations allowed) ----------------
__device__ __align__(16) __half d_x16[(size_t)M_DIM * H_DIM];   //  67 MB
__device__ __align__(16) __half d_w0h[(size_t)H_DIM * I_DIM];   // 117 MB
__device__ __align__(16) __half d_w1h[(size_t)H_DIM * I_DIM];   // 117 MB
__device__ __align__(16) __half d_w2h[(size_t)I_DIM * H_DIM];   // 117 MB (pre-scaled by 64)
__device__ __align__(16) float  d_g  [(size_t)M_DIM * I_DIM];   // 470 MB
__device__ __align__(16) float  d_u  [(size_t)M_DIM * I_DIM];   // 470 MB
__device__ __align__(16) __half d_h16[(size_t)M_DIM * I_DIM];   // 235 MB (h/64 in fp16)

// ---------------- prologue: x fp32 -> fp16 ----------------
__global__ void convert_x_kernel(const float* __restrict__ x) {
    size_t base = ((size_t)blockIdx.x * blockDim.x + threadIdx.x) * 4;
    if (base >= (size_t)M_DIM * H_DIM) return;
    float4 v = *reinterpret_cast<const float4*>(x + base);
    __half2* o = reinterpret_cast<__half2*>(d_x16 + base);
    o[0] = __floats2half2_rn(v.x, v.y);
    o[1] = __floats2half2_rn(v.z, v.w);
}

// ---------------- prologue: dequant int32*scale -> fp16 ----------------
__global__ void dequant_kernel(const int* __restrict__ w, const float* __restrict__ s,
                               __half* __restrict__ out, int cols, float mult, size_t total) {
    size_t base = ((size_t)blockIdx.x * blockDim.x + threadIdx.x) * 4;
    if (base >= total) return;
    int r = (int)(base / (size_t)cols);
    int c = (int)(base % (size_t)cols);
    int4   wv = *reinterpret_cast<const int4*>(w + base);
    float4 sv = *reinterpret_cast<const float4*>(s + (size_t)(r / BSQ) * cols + c);
    __half2* o = reinterpret_cast<__half2*>(out + base);
    o[0] = __floats2half2_rn((float)wv.x * sv.x * mult, (float)wv.y * sv.y * mult);
    o[1] = __floats2half2_rn((float)wv.z * sv.z * mult, (float)wv.w * sv.w * mult);
}

// ---------------- epilogue of stage 1: h = silu(g)*u / 64 -> fp16 ----------------
__global__ void hfuse_kernel() {
    size_t base = ((size_t)blockIdx.x * blockDim.x + threadIdx.x) * 4;
    if (base >= (size_t)M_DIM * I_DIM) return;
    float4 g = *reinterpret_cast<const float4*>(d_g + base);
    float4 u = *reinterpret_cast<const float4*>(d_u + base);
    float h0 = (g.x / (1.0f + __expf(-g.x))) * u.x * 0.015625f;
    float h1 = (g.y / (1.0f + __expf(-g.y))) * u.y * 0.015625f;
    float h2 = (g.z / (1.0f + __expf(-g.z))) * u.z * 0.015625f;
    float h3 = (g.w / (1.0f + __expf(-g.w))) * u.w * 0.015625f;
    __half2* o = reinterpret_cast<__half2*>(d_h16 + base);
    o[0] = __floats2half2_rn(h0, h1);
    o[1] = __floats2half2_rn(h2, h3);
}

// ---------------- WMMA GEMM: C[M,N] = A[M,K] (fp16, rowmaj) * B[K,N] (fp16, rowmaj), fp32 accum ----------------
constexpr int BM = 128, BN = 128, BK = 32;
constexpr int AP = BK + 8;   // padded lds for A tile (16B-aligned rows)
constexpr int BP = BN + 8;   // padded lds for B tile

__global__ __launch_bounds__(256)
void gemm_f16f32(const __half* __restrict__ A, const __half* __restrict__ B,
                 float* __restrict__ C, int M, int N, int K) {
    __shared__ __half As[BM * AP];
    __shared__ __half Bs[BK * BP];

    const int tid  = threadIdx.x;
    const int warp = tid >> 5;
    const int wm   = warp & 1;   // 2 warps along M (64 rows each)
    const int wn   = warp >> 1;  // 4 warps along N (32 cols each)
    const int m0 = blockIdx.y * BM;
    const int n0 = blockIdx.x * BN;

    wmma::fragment<wmma::accumulator, 16, 16, 16, float> acc[4][2];
#pragma unroll
    for (int i = 0; i < 4; i++)
#pragma unroll
        for (int j = 0; j < 2; j++) wmma::fill_fragment(acc[i][j], 0.0f);

    uint4 ra[2], rb[2];

    auto gload = [&](int k0) {
#pragma unroll
        for (int j = 0; j < 2; j++) {
            int v = tid + j * 256;               // 512 uint4 per tile
            int ar = v >> 2, ac = (v & 3) * 8;   // A: 128 rows x 4 vec
            ra[j] = *reinterpret_cast<const uint4*>(A + (size_t)(m0 + ar) * K + (k0 + ac));
            int br = v >> 4, bc = (v & 15) * 8;  // B: 32 rows x 16 vec
            rb[j] = *reinterpret_cast<const uint4*>(B + (size_t)(k0 + br) * N + (n0 + bc));
        }
    };
    auto sstore = [&]() {
#pragma unroll
        for (int j = 0; j < 2; j++) {
            int v = tid + j * 256;
            int ar = v >> 2, ac = (v & 3) * 8;
            *reinterpret_cast<uint4*>(As + ar * AP + ac) = ra[j];
            int br = v >> 4, bc = (v & 15) * 8;
            *reinterpret_cast<uint4*>(Bs + br * BP + bc) = rb[j];
        }
    };

    gload(0);
    sstore();
    __syncthreads();

    const int kT = K / BK;
    for (int t = 0; t < kT; t++) {
        if (t + 1 < kT) gload((t + 1) * BK);   // prefetch next tile into regs

#pragma unroll
        for (int kk = 0; kk < BK; kk += 16) {
            wmma::fragment<wmma::matrix_a, 16, 16, 16, __half, wmma::row_major> af[4];
            wmma::fragment<wmma::matrix_b, 16, 16, 16, __half, wmma::row_major> bf[2];
#pragma unroll
            for (int i = 0; i < 4; i++)
                wmma::load_matrix_sync(af[i], As + (wm * 64 + i * 16) * AP + kk, AP);
#pragma unroll
            for (int j = 0; j < 2; j++)
                wmma::load_matrix_sync(bf[j], Bs + kk * BP + wn * 32 + j * 16, BP);
#pragma unroll
            for (int i = 0; i < 4; i++)
#pragma unroll
                for (int j = 0; j < 2; j++)
                    wmma::mma_sync(acc[i][j], af[i], bf[j], acc[i][j]);
        }
        __syncthreads();
        if (t + 1 < kT) sstore();
        __syncthreads();
    }

#pragma unroll
    for (int i = 0; i < 4; i++)
#pragma unroll
        for (int j = 0; j < 2; j++) {
            int row = m0 + wm * 64 + i * 16;
            int col = n0 + wn * 32 + j * 16;
            wmma::store_matrix_sync(C + (size_t)row * N + col, acc[i][j], N, wmma::mem_row_major);
        }
}

// ---------------- launch ----------------
extern "C" void kernel_launch(void* const* d_in, const int* in_sizes, int n_in,
                              void* d_out, int out_size) {
    const float* x  = (const float*)d_in[0];
    const int*   w0 = (const int*)  d_in[1];
    const int*   w1 = (const int*)  d_in[2];
    const int*   w2 = (const int*)  d_in[3];
    const float* s0 = (const float*)d_in[4];
    const float* s1 = (const float*)d_in[5];
    const float* s2 = (const float*)d_in[6];
    float* out = (float*)d_out;

    __half *px16, *pw0, *pw1, *pw2, *ph16;
    float  *pg, *pu;
    cudaGetSymbolAddress((void**)&px16, d_x16);
    cudaGetSymbolAddress((void**)&pw0,  d_w0h);
    cudaGetSymbolAddress((void**)&pw1,  d_w1h);
    cudaGetSymbolAddress((void**)&pw2,  d_w2h);
    cudaGetSymbolAddress((void**)&pg,   d_g);
    cudaGetSymbolAddress((void**)&pu,   d_u);
    cudaGetSymbolAddress((void**)&ph16, d_h16);

    const size_t xTot = (size_t)M_DIM * H_DIM;            // 33.5M
    const size_t wTot = (size_t)H_DIM * I_DIM;            // 58.7M (same for w2)
    const size_t hTot = (size_t)M_DIM * I_DIM;            // 117.4M

    convert_x_kernel<<<(unsigned)(xTot / 4 / 256), 256>>>(x);
    dequant_kernel<<<(unsigned)(wTot / 4 / 256), 256>>>(w0, s0, pw0, I_DIM, 1.0f,  wTot);
    dequant_kernel<<<(unsigned)(wTot / 4 / 256), 256>>>(w1, s1, pw1, I_DIM, 1.0f,  wTot);
    dequant_kernel<<<(unsigned)(wTot / 4 / 256), 256>>>(w2, s2, pw2, H_DIM, 64.0f, wTot);

    dim3 grid1(I_DIM / BN, M_DIM / BM);   // (112, 64)
    gemm_f16f32<<<grid1, 256>>>(px16, pw0, pg, M_DIM, I_DIM, H_DIM);
    gemm_f16f32<<<grid1, 256>>>(px16, pw1, pu, M_DIM, I_DIM, H_DIM);

    hfuse_kernel<<<(unsigned)(hTot / 4 / 256), 256>>>();

    dim3 grid2(H_DIM / BN, M_DIM / BM);   // (32, 64)
    gemm_f16f32<<<grid2, 256>>>(ph16, pw2, out, M_DIM, H_DIM, I_DIM);
}

// round 5
// speedup vs baseline: 1.3005x; 1.3005x over previous
#include <cuda_runtime.h>
#include <cuda_fp16.h>
#include <cstdint>

#define H_DIM 4096
#define I_DIM 14336
#define M_DIM 8192   // B*S
#define BSQ   128

// ---------------- static device scratch ----------------
__device__ __align__(16) __half d_x16[(size_t)M_DIM * H_DIM];   // x fp16 [M,H] K-major
__device__ __align__(16) __half d_w0t[(size_t)I_DIM * H_DIM];   // W0^T [I,H] K-major
__device__ __align__(16) __half d_w1t[(size_t)I_DIM * H_DIM];   // W1^T [I,H]
__device__ __align__(16) __half d_w2t[(size_t)H_DIM * I_DIM];   // W2^T [H,I] (x64)
__device__ __align__(16) __half d_h16[(size_t)M_DIM * I_DIM];   // h/64 fp16 [M,I]

// ---------------- PTX helpers ----------------
__device__ __forceinline__ uint32_t smem_u32(const void* p) {
    uint32_t a;
    asm("{ .reg .u64 t; cvta.to.shared.u64 t, %1; cvt.u32.u64 %0, t; }" : "=r"(a) : "l"(p));
    return a;
}
#define CP16(s, g)   asm volatile("cp.async.cg.shared.global [%0], [%1], 16;" :: "r"(s), "l"(g))
#define CP_COMMIT()  asm volatile("cp.async.commit_group;" ::: "memory")
template<int N> __device__ __forceinline__ void cp_wait() {
    asm volatile("cp.async.wait_group %0;" :: "n"(N) : "memory");
}
#define LDSM4(r0, r1, r2, r3, a) \
    asm volatile("ldmatrix.sync.aligned.m8n8.x4.shared.b16 {%0,%1,%2,%3}, [%4];" \
        : "=r"(r0), "=r"(r1), "=r"(r2), "=r"(r3) : "r"(a))
#define MMA16816(c0, c1, c2, c3, a0, a1, a2, a3, b0, b1) \
    asm volatile("mma.sync.aligned.m16n8k16.row.col.f32.f16.f16.f32 " \
        "{%0,%1,%2,%3}, {%4,%5,%6,%7}, {%8,%9}, {%0,%1,%2,%3};" \
        : "+f"(c0), "+f"(c1), "+f"(c2), "+f"(c3) \
        : "r"(a0), "r"(a1), "r"(a2), "r"(a3), "r"(b0), "r"(b1))

// ---------------- prologue: x fp32 -> fp16 ----------------
__global__ void convert_x_kernel(const float* __restrict__ x) {
    size_t base = ((size_t)blockIdx.x * blockDim.x + threadIdx.x) * 4;
    if (base >= (size_t)M_DIM * H_DIM) return;
    float4 v = *reinterpret_cast<const float4*>(x + base);
    __half2* o = reinterpret_cast<__half2*>(d_x16 + base);
    o[0] = __floats2half2_rn(v.x, v.y);
    o[1] = __floats2half2_rn(v.z, v.w);
}

// ---------------- dequant + transpose: w[K,N] int32 -> out[N,K] fp16 ----------------
__global__ __launch_bounds__(256)
void dequantT_kernel(const int* __restrict__ w, const float* __restrict__ s,
                     __half* __restrict__ out, int Kd, int Nd, float mult) {
    __shared__ __half tile[64][72];
    const int n0 = blockIdx.x * 64, k0 = blockIdx.y * 64;
    const int tid = threadIdx.x;
    const int sr = k0 / BSQ;
#pragma unroll
    for (int i = 0; i < 4; i++) {
        int v = tid + i * 256;
        int r = v >> 4, c4 = (v & 15) * 4;
        int4   wv = *reinterpret_cast<const int4*>(w + (size_t)(k0 + r) * Nd + n0 + c4);
        float4 sv = *reinterpret_cast<const float4*>(s + (size_t)sr * Nd + n0 + c4);
        tile[r][c4 + 0] = __float2half_rn((float)wv.x * sv.x * mult);
        tile[r][c4 + 1] = __float2half_rn((float)wv.y * sv.y * mult);
        tile[r][c4 + 2] = __float2half_rn((float)wv.z * sv.z * mult);
        tile[r][c4 + 3] = __float2half_rn((float)wv.w * sv.w * mult);
    }
    __syncthreads();
#pragma unroll
    for (int i = 0; i < 2; i++) {
        int v = tid + i * 256;
        int nr = v >> 3, kc = (v & 7) * 8;
        __align__(16) __half tmp[8];
#pragma unroll
        for (int e = 0; e < 8; e++) tmp[e] = tile[kc + e][nr];
        *reinterpret_cast<uint4*>(out + (size_t)(n0 + nr) * Kd + k0 + kc) =
            *reinterpret_cast<const uint4*>(tmp);
    }
}

// ---------------- stage loader: A[128,64] + NMATS x B[128,64], XOR-swizzled 128B rows ----------------
template<int NMATS>
__device__ __forceinline__ void load_stage(uint32_t tbuf, const __half* A, const __half* B0,
                                           const __half* B1, int m0, int n0, int K, int chunk, int tid) {
    const size_t rowb = (size_t)K * 2;
    const char* ag = (const char*)(A + (size_t)m0 * K + (size_t)chunk * 64);
#pragma unroll
    for (int j = 0; j < 2; j++) {
        int v = tid + j * 512, r = v >> 3, cs = v & 7, csw = cs ^ (r & 7);
        CP16(tbuf + r * 128 + csw * 16, ag + r * rowb + cs * 16);
    }
    const char* bg0 = (const char*)(B0 + (size_t)n0 * K + (size_t)chunk * 64);
#pragma unroll
    for (int j = 0; j < 2; j++) {
        int v = tid + j * 512, r = v >> 3, cs = v & 7, csw = cs ^ (r & 7);
        CP16(tbuf + 16384 + r * 128 + csw * 16, bg0 + r * rowb + cs * 16);
    }
    if (NMATS == 2) {
        const char* bg1 = (const char*)(B1 + (size_t)n0 * K + (size_t)chunk * 64);
#pragma unroll
        for (int j = 0; j < 2; j++) {
            int v = tid + j * 512, r = v >> 3, cs = v & 7, csw = cs ^ (r & 7);
            CP16(tbuf + 32768 + r * 128 + csw * 16, bg1 + r * rowb + cs * 16);
        }
    }
}

// ---------------- HMMA GEMM: D[M,N] = A[M,K] x B[N,K]^T ----------------
// NMATS=2 + FUSE: D0=A*B0^T, D1=A*B1^T, out fp16 = silu(D0)*D1/64
// NMATS=1: out fp32 = D0
template<int NMATS, bool FUSE, int STAGES>
__global__ __launch_bounds__(512, 1)
void hmma_gemm(const __half* __restrict__ A, const __half* __restrict__ Bm0,
               const __half* __restrict__ Bm1, void* __restrict__ Cout,
               int M, int N, int K) {
    constexpr int STAGE_BYTES = (1 + NMATS) * 16384;
    extern __shared__ char smem[];
    const uint32_t sbase = smem_u32(smem);
    const int tid = threadIdx.x, wid = tid >> 5, lane = tid & 31;
    const int wm = wid & 3, wn = wid >> 2;           // 4x4 warp grid, 32x32 warp tiles
    const int row_in = lane & 7, sel = lane >> 3;

    // GROUP_M=16 swizzled tile mapping (L2 locality)
    const int ntn = N >> 7;
    const int per_band = 16 * ntn;
    const int band = blockIdx.x / per_band, rem = blockIdx.x % per_band;
    const int m0 = (band * 16 + (rem & 15)) << 7;
    const int n0 = (rem >> 4) << 7;

    float acc[NMATS][2][4][4];
#pragma unroll
    for (int t = 0; t < NMATS; t++)
#pragma unroll
        for (int mi = 0; mi < 2; mi++)
#pragma unroll
            for (int j = 0; j < 4; j++)
#pragma unroll
                for (int e = 0; e < 4; e++) acc[t][mi][j][e] = 0.0f;

    const int NCH = K >> 6;

    // prologue: fill STAGES-1 stages
#pragma unroll
    for (int c = 0; c < STAGES - 1; c++) {
        load_stage<NMATS>(sbase + c * STAGE_BYTES, A, Bm0, Bm1, m0, n0, K, c, tid);
        CP_COMMIT();
    }

    // precomputed per-lane fragment addressing (within-stage offsets)
    //   A frag (16x16 tile): row = mbase + (sel&1)*8 + row_in, c16 = kkc + (sel>>1)
    //   B frag (16n x 16k):  row = nbase + (sel>>1)*8 + row_in, c16 = kkc + (sel&1)
    const int a_row_base = wm * 32 + ((sel & 1) << 3) + row_in;
    const int a_c16_add  = sel >> 1;
    const int b_row_base = wn * 32 + ((sel >> 1) << 3) + row_in;
    const int b_c16_add  = sel & 1;

    for (int c = 0; c < NCH; c++) {
        cp_wait<STAGES - 2>();
        __syncthreads();
        const int lc = c + STAGES - 1;
        if (lc < NCH)
            load_stage<NMATS>(sbase + (lc % STAGES) * STAGE_BYTES, A, Bm0, Bm1, m0, n0, K, lc, tid);
        CP_COMMIT();

        const uint32_t sb = sbase + (c % STAGES) * STAGE_BYTES;
#pragma unroll
        for (int ks = 0; ks < 4; ks++) {
            const int kkc = ks * 2;
            uint32_t a[2][4];
#pragma unroll
            for (int mi = 0; mi < 2; mi++) {
                int r = a_row_base + mi * 16;
                int c16 = kkc + a_c16_add;
                uint32_t ad = sb + r * 128 + (((uint32_t)(c16 ^ (r & 7))) << 4);
                LDSM4(a[mi][0], a[mi][1], a[mi][2], a[mi][3], ad);
            }
#pragma unroll
            for (int t = 0; t < NMATS; t++) {
#pragma unroll
                for (int p = 0; p < 2; p++) {
                    int r = b_row_base + p * 16;
                    int c16 = kkc + b_c16_add;
                    uint32_t bd = sb + 16384 + t * 16384 + r * 128 +
                                  (((uint32_t)(c16 ^ (r & 7))) << 4);
                    uint32_t q0, q1, q2, q3;
                    LDSM4(q0, q1, q2, q3, bd);
#pragma unroll
                    for (int mi = 0; mi < 2; mi++) {
                        float* c0 = acc[t][mi][2 * p];
                        float* c1 = acc[t][mi][2 * p + 1];
                        MMA16816(c0[0], c0[1], c0[2], c0[3],
                                 a[mi][0], a[mi][1], a[mi][2], a[mi][3], q0, q1);
                        MMA16816(c1[0], c1[1], c1[2], c1[3],
                                 a[mi][0], a[mi][1], a[mi][2], a[mi][3], q2, q3);
                    }
                }
            }
        }
    }

    // epilogue: c-frag thread mapping: c0,c1 -> (row gid, col 2*(lane%4)); c2,c3 -> row gid+8
    const int gid = lane >> 2;
    const int cpair = (lane & 3) * 2;
    if (FUSE) {
        __half* Ch = (__half*)Cout;
#pragma unroll
        for (int mi = 0; mi < 2; mi++) {
#pragma unroll
            for (int j = 0; j < 4; j++) {
                int rr = m0 + wm * 32 + mi * 16 + gid;
                int cc = n0 + wn * 32 + j * 8 + cpair;
                const float* g = acc[0][mi][j];
                const float* u = acc[1][mi][j];
                float h0 = g[0] / (1.0f + __expf(-g[0])) * u[0] * 0.015625f;
                float h1 = g[1] / (1.0f + __expf(-g[1])) * u[1] * 0.015625f;
                float h2 = g[2] / (1.0f + __expf(-g[2])) * u[2] * 0.015625f;
                float h3 = g[3] / (1.0f + __expf(-g[3])) * u[3] * 0.015625f;
                *reinterpret_cast<__half2*>(Ch + (size_t)rr * N + cc) = __floats2half2_rn(h0, h1);
                *reinterpret_cast<__half2*>(Ch + (size_t)(rr + 8) * N + cc) = __floats2half2_rn(h2, h3);
            }
        }
    } else {
        float* Cf = (float*)Cout;
#pragma unroll
        for (int mi = 0; mi < 2; mi++) {
#pragma unroll
            for (int j = 0; j < 4; j++) {
                int rr = m0 + wm * 32 + mi * 16 + gid;
                int cc = n0 + wn * 32 + j * 8 + cpair;
                const float* d = acc[0][mi][j];
                *reinterpret_cast<float2*>(Cf + (size_t)rr * N + cc) = make_float2(d[0], d[1]);
                *reinterpret_cast<float2*>(Cf + (size_t)(rr + 8) * N + cc) = make_float2(d[2], d[3]);
            }
        }
    }
}

// ---------------- launch ----------------
extern "C" void kernel_launch(void* const* d_in, const int* in_sizes, int n_in,
                              void* d_out, int out_size) {
    const float* x  = (const float*)d_in[0];
    const int*   w0 = (const int*)  d_in[1];
    const int*   w1 = (const int*)  d_in[2];
    const int*   w2 = (const int*)  d_in[3];
    const float* s0 = (const float*)d_in[4];
    const float* s1 = (const float*)d_in[5];
    const float* s2 = (const float*)d_in[6];
    float* out = (float*)d_out;

    __half *px16, *pw0t, *pw1t, *pw2t, *ph16;
    cudaGetSymbolAddress((void**)&px16, d_x16);
    cudaGetSymbolAddress((void**)&pw0t, d_w0t);
    cudaGetSymbolAddress((void**)&pw1t, d_w1t);
    cudaGetSymbolAddress((void**)&pw2t, d_w2t);
    cudaGetSymbolAddress((void**)&ph16, d_h16);

    const size_t xTot = (size_t)M_DIM * H_DIM;
    convert_x_kernel<<<(unsigned)(xTot / 4 / 256), 256>>>(x);

    dequantT_kernel<<<dim3(I_DIM / 64, H_DIM / 64), 256>>>(w0, s0, pw0t, H_DIM, I_DIM, 1.0f);
    dequantT_kernel<<<dim3(I_DIM / 64, H_DIM / 64), 256>>>(w1, s1, pw1t, H_DIM, I_DIM, 1.0f);
    dequantT_kernel<<<dim3(H_DIM / 64, I_DIM / 64), 256>>>(w2, s2, pw2t, I_DIM, H_DIM, 64.0f);

    // GEMM1: dual-B (gate+up) + silu fusion -> h16, 3 stages x 48KB
    const int smem1 = 3 * (3 * 16384);   // 147456
    cudaFuncSetAttribute(hmma_gemm<2, true, 3>, cudaFuncAttributeMaxDynamicSharedMemorySize, smem1);
    hmma_gemm<2, true, 3><<<(M_DIM / 128) * (I_DIM / 128), 512, smem1>>>(
        px16, pw0t, pw1t, ph16, M_DIM, I_DIM, H_DIM);

    // GEMM2: h16 x W2^T -> out fp32, 4 stages x 32KB
    const int smem2 = 4 * (2 * 16384);   // 131072
    cudaFuncSetAttribute(hmma_gemm<1, false, 4>, cudaFuncAttributeMaxDynamicSharedMemorySize, smem2);
    hmma_gemm<1, false, 4><<<(M_DIM / 128) * (H_DIM / 128), 512, smem2>>>(
        ph16, pw2t, (const __half*)nullptr, out, M_DIM, H_DIM, I_DIM);
}